// round 5
// baseline (speedup 1.0000x reference)
#include <cuda_runtime.h>

// Problem constants
#define Bn   4
#define Hq   512
#define Wq   512
#define Cn   128
#define Hon  502
#define Won  502
#define OFFS 2
// Tiling
#define TH   8      // output rows per block
#define TW   64     // output cols per block
#define WT   4      // output cols per thread
#define CCK  8      // channel chunk
#define QW   72     // TW + 8 (halo)
#define QR   10     // q rows per dy-group: TH + 2
#define PPAD 68     // padded p width
#define QPAD 76     // padded q width
#define NTX  16
#define NTY  8
#define NTHR 128

// Packed fp32x2 helpers (sm_103a)
#define FMA2(d, a, b) asm("fma.rn.f32x2 %0, %1, %2, %0;" : "+l"(d) : "l"(a), "l"(b))
#define PACK2(r, lo, hi) asm("mov.b64 %0, {%1, %2};" : "=l"(r) : "f"(lo), "f"(hi))
#define UNPACK2(lo, hi, r) asm("mov.b64 {%0, %1}, %2;" : "=f"(lo), "=f"(hi) : "l"(r))

__global__ __launch_bounds__(NTHR, 3)
void corr9x9_kernel(const float* __restrict__ pg,
                    const float* __restrict__ qg,
                    float* __restrict__ outg)
{
    __shared__ __align__(16) float p_s[TH][CCK][PPAD];
    __shared__ __align__(16) float q_s[QR][CCK][QPAD];

    const int tx  = threadIdx.x;
    const int ty  = threadIdx.y;
    const int tid = ty * NTX + tx;

    const int wo0 = blockIdx.x * TW;
    const int ho0 = blockIdx.y * TH;
    const int b   = blockIdx.z;

    const float* pb = pg + (size_t)b * Hon * Won * Cn;
    const float* qb = qg + (size_t)b * Hq  * Wq  * Cn;

    const int ho = ho0 + ty;

    // ---- precompute staging addresses (constant across chunks/groups) ----
    // p staging: 8 iterations
    const float* p_src[8];
    int p_c4[8], p_w[8], p_row[8];
    #pragma unroll
    for (int it = 0; it < 8; ++it) {
        int flat = tid + it * NTHR;
        int c4   = flat & 1;
        int w    = (flat >> 1) & (TW - 1);
        int row  = flat >> 7;
        int hr   = ho0 + row; if (hr > Hon - 1) hr = Hon - 1;
        int wr   = wo0 + w;   if (wr > Won - 1) wr = Won - 1;
        p_src[it] = pb + ((size_t)hr * Won + wr) * Cn + c4 * 4;
        p_c4[it] = c4; p_w[it] = w; p_row[it] = row;
    }

    for (int g = 0; g < 3; ++g) {
        // packed accumulators: pixel pairs (0,1) and (2,3); [pair][d][dx]
        unsigned long long acc[2][3][9];
        #pragma unroll
        for (int k = 0; k < 2; ++k)
            #pragma unroll
            for (int d = 0; d < 3; ++d)
                #pragma unroll
                for (int dx = 0; dx < 9; ++dx)
                    acc[k][d][dx] = 0ull;

        const int r0 = ho0 + 3 * g + OFFS;

        for (int cc = 0; cc < Cn; cc += CCK) {
            __syncthreads();

            // ---- stage p: batch all 8 LDGs, then STS ----
            {
                float4 pv[8];
                #pragma unroll
                for (int it = 0; it < 8; ++it)
                    pv[it] = *(const float4*)(p_src[it] + cc);
                #pragma unroll
                for (int it = 0; it < 8; ++it) {
                    p_s[p_row[it]][p_c4[it] * 4 + 0][p_w[it]] = pv[it].x;
                    p_s[p_row[it]][p_c4[it] * 4 + 1][p_w[it]] = pv[it].y;
                    p_s[p_row[it]][p_c4[it] * 4 + 2][p_w[it]] = pv[it].z;
                    p_s[p_row[it]][p_c4[it] * 4 + 3][p_w[it]] = pv[it].w;
                }
            }

            // ---- stage q: two batches of 6 ----
            #pragma unroll
            for (int half = 0; half < 2; ++half) {
                float4 qv[6];
                int qc4[6], qw[6], qrr[6];
                bool ok[6];
                #pragma unroll
                for (int j = 0; j < 6; ++j) {
                    int flat = tid + (half * 6 + j) * NTHR;
                    ok[j] = (flat < QR * QW * 2);
                    int f  = ok[j] ? flat : 0;
                    int c4 = f & 1;
                    int t  = f >> 1;
                    int w  = t % QW;
                    int rr = t / QW;
                    int hr = r0 + rr;        if (hr > Hq - 1) hr = Hq - 1;
                    int wr = wo0 + OFFS + w; if (wr > Wq - 1) wr = Wq - 1;
                    qc4[j] = c4; qw[j] = w; qrr[j] = rr;
                    if (ok[j])
                        qv[j] = *(const float4*)(qb + ((size_t)hr * Wq + wr) * Cn + cc + c4 * 4);
                }
                #pragma unroll
                for (int j = 0; j < 6; ++j) {
                    if (ok[j]) {
                        q_s[qrr[j]][qc4[j] * 4 + 0][qw[j]] = qv[j].x;
                        q_s[qrr[j]][qc4[j] * 4 + 1][qw[j]] = qv[j].y;
                        q_s[qrr[j]][qc4[j] * 4 + 2][qw[j]] = qv[j].z;
                        q_s[qrr[j]][qc4[j] * 4 + 3][qw[j]] = qv[j].w;
                    }
                }
            }

            __syncthreads();

            // ---- packed compute ----
            #pragma unroll
            for (int c = 0; c < CCK; ++c) {
                const float4 pv = *(const float4*)&p_s[ty][c][tx * WT];
                unsigned long long pp2[2];
                PACK2(pp2[0], pv.x, pv.y);
                PACK2(pp2[1], pv.z, pv.w);

                #pragma unroll
                for (int d = 0; d < 3; ++d) {
                    const float4 a0 = *(const float4*)&q_s[ty + d][c][tx * WT];
                    const float4 a1 = *(const float4*)&q_s[ty + d][c][tx * WT + 4];
                    const float4 a2 = *(const float4*)&q_s[ty + d][c][tx * WT + 8];
                    float qv[12] = {a0.x, a0.y, a0.z, a0.w,
                                    a1.x, a1.y, a1.z, a1.w,
                                    a2.x, a2.y, a2.z, a2.w};
                    // pairs pr[j] = (qv[j], qv[j+1]) for j = 0..10
                    unsigned long long pr[11];
                    #pragma unroll
                    for (int j = 0; j < 11; ++j)
                        PACK2(pr[j], qv[j], qv[j + 1]);

                    #pragma unroll
                    for (int dx = 0; dx < 9; ++dx) {
                        FMA2(acc[0][d][dx], pp2[0], pr[dx]);       // pixels 0,1
                        FMA2(acc[1][d][dx], pp2[1], pr[dx + 2]);   // pixels 2,3
                    }
                }
            }
        }

        // ---- write outputs for this dy-group ----
        if (ho < Hon) {
            #pragma unroll
            for (int k = 0; k < 2; ++k) {
                int wo_lo = wo0 + tx * WT + 2 * k;
                int wo_hi = wo_lo + 1;
                #pragma unroll
                for (int d = 0; d < 3; ++d) {
                    size_t base_lo = ((((size_t)b * Hon + ho) * Won + wo_lo) * 9 + (3 * g + d)) * 9;
                    size_t base_hi = ((((size_t)b * Hon + ho) * Won + wo_hi) * 9 + (3 * g + d)) * 9;
                    #pragma unroll
                    for (int dx = 0; dx < 9; ++dx) {
                        float lo, hi;
                        UNPACK2(lo, hi, acc[k][d][dx]);
                        if (wo_lo < Won) __stcs(&outg[base_lo + dx], lo);
                        if (wo_hi < Won) __stcs(&outg[base_hi + dx], hi);
                    }
                }
            }
        }
    }
}

extern "C" void kernel_launch(void* const* d_in, const int* in_sizes, int n_in,
                              void* d_out, int out_size)
{
    const float* p = (const float*)d_in[0];
    const float* q = (const float*)d_in[1];
    float* out = (float*)d_out;

    dim3 block(NTX, NTY);
    dim3 grid((Won + TW - 1) / TW,   // 8
              (Hon + TH - 1) / TH,   // 63
              Bn);                   // 4
    corr9x9_kernel<<<grid, block>>>(p, q, out);
}

// round 6
// speedup vs baseline: 1.5580x; 1.5580x over previous
#include <cuda_runtime.h>

// Problem constants
#define Bn   4
#define Hq   512
#define Wq   512
#define Cn   128
#define Hon  502
#define Won  502
#define OFFS 2
// Tiling: block (8,4,9); tile 4 rows x 64 cols; tz == dy
#define TH   4
#define TW   64
#define NTX  8
#define NTZ  9
#define NTHR 288
#define CCK  8
#define NCHUNK 16
#define QR   12            // TH + 8 halo rows
#define QW   72            // TW + 8 halo cols
#define QPAD 76
#define PPAD 68

// union sizes (floats)
#define TILE_FLOATS (QR*CCK*QPAD + TH*CCK*PPAD)   // 7296 + 2176 = 9472
#define OUTS_FLOATS (2*TW*81)                     // 10368
#define SMEM_FLOATS (OUTS_FLOATS > TILE_FLOATS ? OUTS_FLOATS : TILE_FLOATS)

// Packed fp32x2 helpers (sm_103a)
#define FMA2(d, a, b) asm("fma.rn.f32x2 %0, %1, %2, %0;" : "+l"(d) : "l"(a), "l"(b))
#define PACK2(r, lo, hi) asm("mov.b64 %0, {%1, %2};" : "=l"(r) : "f"(lo), "f"(hi))
#define UNPACK2(lo, hi, r) asm("mov.b64 {%0, %1}, %2;" : "=f"(lo), "=f"(hi) : "l"(r))

__global__ __launch_bounds__(NTHR, 1)
void corr9x9_sp_kernel(const float* __restrict__ pg,
                       const float* __restrict__ qg,
                       float* __restrict__ outg)
{
    __shared__ __align__(16) float smem[SMEM_FLOATS];
    float* q_s = smem;                       // [QR][CCK][QPAD]
    float* p_s = smem + QR * CCK * QPAD;     // [TH][CCK][PPAD]

    const int tx  = threadIdx.x;             // 0..7
    const int ty  = threadIdx.y;             // 0..3
    const int tz  = threadIdx.z;             // 0..8 == dy
    const int tid = tx + NTX * (ty + TH * tz);

    const int wo0 = blockIdx.x * TW;
    const int ho0 = blockIdx.y * TH;
    const int b   = blockIdx.z;

    const float* pb = pg + (size_t)b * Hon * Won * Cn;
    const float* qb = qg + (size_t)b * Hq  * Wq  * Cn;

    // ---- precompute staging offsets ----
    int qoff[6], qdst[6];
    #pragma unroll
    for (int i = 0; i < 6; ++i) {
        int flat = tid + i * NTHR;          // exactly covers QR*QW*2 = 1728
        int c4   = flat & 1;
        int t    = flat >> 1;
        int w    = t % QW;
        int rr   = t / QW;
        int hr   = ho0 + OFFS + rr; if (hr > Hq - 1) hr = Hq - 1;
        int wr   = wo0 + OFFS + w;  if (wr > Wq - 1) wr = Wq - 1;
        qoff[i]  = (hr * Wq + wr) * Cn + c4 * 4;
        qdst[i]  = (rr * CCK + c4 * 4) * QPAD + w;
    }
    int poff[2], pdst[2];
    bool pok[2];
    #pragma unroll
    for (int i = 0; i < 2; ++i) {
        int flat = tid + i * NTHR;
        pok[i]  = (flat < TH * TW * 2);      // 512
        int f   = pok[i] ? flat : 0;
        int c4  = f & 1;
        int t   = f >> 1;
        int w   = t & (TW - 1);
        int rw  = t >> 6;
        int hr  = ho0 + rw; if (hr > Hon - 1) hr = Hon - 1;
        int wr  = wo0 + w;  if (wr > Won - 1) wr = Won - 1;
        poff[i] = (hr * Won + wr) * Cn + c4 * 4;
        pdst[i] = (rw * CCK + c4 * 4) * PPAD + w;
    }

    // ---- accumulators: [group][pair][dx], packed f32x2 ----
    unsigned long long acc[2][2][9];
    #pragma unroll
    for (int g = 0; g < 2; ++g)
        #pragma unroll
        for (int j = 0; j < 2; ++j)
            #pragma unroll
            for (int dx = 0; dx < 9; ++dx)
                acc[g][j][dx] = 0ull;

    const int r = ty + tz;                   // q tile row for this thread

    // ---- prolog: prefetch chunk 0 ----
    float4 qpf[6], ppf[2];
    #pragma unroll
    for (int i = 0; i < 6; ++i)
        qpf[i] = *(const float4*)(qb + qoff[i]);
    #pragma unroll
    for (int i = 0; i < 2; ++i)
        if (pok[i]) ppf[i] = *(const float4*)(pb + poff[i]);

    for (int k = 0; k < NCHUNK; ++k) {
        __syncthreads();    // protect smem from previous chunk's readers
        // ---- STS chunk k ----
        #pragma unroll
        for (int i = 0; i < 6; ++i) {
            q_s[qdst[i]           ] = qpf[i].x;
            q_s[qdst[i] +     QPAD] = qpf[i].y;
            q_s[qdst[i] + 2 * QPAD] = qpf[i].z;
            q_s[qdst[i] + 3 * QPAD] = qpf[i].w;
        }
        #pragma unroll
        for (int i = 0; i < 2; ++i) {
            if (pok[i]) {
                p_s[pdst[i]           ] = ppf[i].x;
                p_s[pdst[i] +     PPAD] = ppf[i].y;
                p_s[pdst[i] + 2 * PPAD] = ppf[i].z;
                p_s[pdst[i] + 3 * PPAD] = ppf[i].w;
            }
        }
        __syncthreads();

        // ---- prefetch chunk k+1 (issued before compute to maximize MLP) ----
        if (k + 1 < NCHUNK) {
            int cc = (k + 1) * CCK;
            #pragma unroll
            for (int i = 0; i < 6; ++i)
                qpf[i] = *(const float4*)(qb + qoff[i] + cc);
            #pragma unroll
            for (int i = 0; i < 2; ++i)
                if (pok[i]) ppf[i] = *(const float4*)(pb + poff[i] + cc);
        }

        // ---- compute chunk k ----
        #pragma unroll
        for (int c = 0; c < CCK; ++c) {
            const float* qrow = q_s + (r * CCK + c) * QPAD;
            const float* prow = p_s + (ty * CCK + c) * PPAD;
            #pragma unroll
            for (int g = 0; g < 2; ++g) {
                const int w0 = g * 32 + tx * 4;
                const float4 pv = *(const float4*)(prow + w0);
                unsigned long long pp[2];
                PACK2(pp[0], pv.x, pv.y);
                PACK2(pp[1], pv.z, pv.w);

                const float4 a0 = *(const float4*)(qrow + w0);
                const float4 a1 = *(const float4*)(qrow + w0 + 4);
                const float4 a2 = *(const float4*)(qrow + w0 + 8);
                float qf[12] = {a0.x, a0.y, a0.z, a0.w,
                                a1.x, a1.y, a1.z, a1.w,
                                a2.x, a2.y, a2.z, a2.w};
                unsigned long long pr[11];
                #pragma unroll
                for (int j = 0; j < 11; ++j)
                    PACK2(pr[j], qf[j], qf[j + 1]);

                #pragma unroll
                for (int dx = 0; dx < 9; ++dx) {
                    FMA2(acc[g][0][dx], pp[0], pr[dx]);       // pixels w0+0,1
                    FMA2(acc[g][1][dx], pp[1], pr[dx + 2]);   // pixels w0+2,3
                }
            }
        }
    }

    // ---- epilogue: smem-staged coalesced output, 2 slabs of 2 rows ----
    float* out_s = smem;    // [2][TW][81] = 10368 floats
    #pragma unroll
    for (int s = 0; s < 2; ++s) {
        __syncthreads();
        if ((ty >> 1) == s) {
            const int rr = ty & 1;
            #pragma unroll
            for (int g = 0; g < 2; ++g) {
                const int w0 = g * 32 + tx * 4;
                #pragma unroll
                for (int j = 0; j < 2; ++j) {
                    // pixels w0+2j, w0+2j+1
                    float* d0 = out_s + (rr * TW + w0 + 2 * j) * 81 + tz * 9;
                    float* d1 = d0 + 81;
                    #pragma unroll
                    for (int dx = 0; dx < 9; ++dx) {
                        float lo, hi;
                        UNPACK2(lo, hi, acc[g][j][dx]);
                        d0[dx] = lo;
                        d1[dx] = hi;
                    }
                }
            }
        }
        __syncthreads();
        // cooperative coalesced copy: 10368 floats, 36 per thread
        #pragma unroll
        for (int kk = 0; kk < 36; ++kk) {
            int f   = tid + kk * NTHR;
            int rr  = f / (TW * 81);
            int rem = f - rr * (TW * 81);
            int px  = rem / 81;
            int ho  = ho0 + 2 * s + rr;
            if (ho < Hon && (wo0 + px) < Won) {
                size_t dst = ((size_t)(b * Hon + ho) * Won + wo0) * 81 + rem;
                __stcs(&outg[dst], out_s[f]);
            }
        }
    }
}

extern "C" void kernel_launch(void* const* d_in, const int* in_sizes, int n_in,
                              void* d_out, int out_size)
{
    const float* p = (const float*)d_in[0];
    const float* q = (const float*)d_in[1];
    float* out = (float*)d_out;

    dim3 block(NTX, TH, NTZ);                  // 8 x 4 x 9 = 288
    dim3 grid((Won + TW - 1) / TW,             // 8
              (Hon + TH - 1) / TH,             // 126
              Bn);                             // 4
    corr9x9_sp_kernel<<<grid, block>>>(p, q, out);
}

// round 7
// speedup vs baseline: 1.5587x; 1.0004x over previous
#include <cuda_runtime.h>

// Problem constants
#define Bn   4
#define Hq   512
#define Wq   512
#define Cn   128
#define Hon  502
#define Won  502
#define OFFS 2
// Tiling: block (8,4,9); tile 4 rows x 64 cols; tz == dy
#define TH   4
#define TW   64
#define NTX  8
#define NTZ  9
#define NTHR 288
#define CCK  8
#define NCHUNK 16
#define QR   12            // TH + 8 halo rows
#define QW   72            // TW + 8 halo cols
#define QPAD 76
#define PPAD 68

// union sizes (floats)
#define TILE_FLOATS (QR*CCK*QPAD + TH*CCK*PPAD)   // 7296 + 2176 = 9472
#define OUTS_FLOATS (2*TW*81)                     // 10368
#define SMEM_FLOATS (OUTS_FLOATS > TILE_FLOATS ? OUTS_FLOATS : TILE_FLOATS)

// Packed fp32x2 helpers (sm_103a)
#define FMA2(d, a, b) asm("fma.rn.f32x2 %0, %1, %2, %0;" : "+l"(d) : "l"(a), "l"(b))
#define PACK2(r, lo, hi) asm("mov.b64 %0, {%1, %2};" : "=l"(r) : "f"(lo), "f"(hi))
#define UNPACK2(lo, hi, r) asm("mov.b64 {%0, %1}, %2;" : "=f"(lo), "=f"(hi) : "l"(r))

__global__ __launch_bounds__(NTHR, 1)
void corr9x9_sp_kernel(const float* __restrict__ pg,
                       const float* __restrict__ qg,
                       float* __restrict__ outg)
{
    __shared__ __align__(16) float smem[SMEM_FLOATS];
    float* q_s = smem;                       // [QR][CCK][QPAD]
    float* p_s = smem + QR * CCK * QPAD;     // [TH][CCK][PPAD]

    const int tx  = threadIdx.x;             // 0..7
    const int ty  = threadIdx.y;             // 0..3
    const int tz  = threadIdx.z;             // 0..8 == dy
    const int tid = tx + NTX * (ty + TH * tz);

    const int wo0 = blockIdx.x * TW;
    const int ho0 = blockIdx.y * TH;
    const int b   = blockIdx.z;

    const float* pb = pg + (size_t)b * Hon * Won * Cn;
    const float* qb = qg + (size_t)b * Hq  * Wq  * Cn;

    // ---- precompute staging offsets ----
    int qoff[6], qdst[6];
    #pragma unroll
    for (int i = 0; i < 6; ++i) {
        int flat = tid + i * NTHR;          // exactly covers QR*QW*2 = 1728
        int c4   = flat & 1;
        int t    = flat >> 1;
        int w    = t % QW;
        int rr   = t / QW;
        int hr   = ho0 + OFFS + rr; if (hr > Hq - 1) hr = Hq - 1;
        int wr   = wo0 + OFFS + w;  if (wr > Wq - 1) wr = Wq - 1;
        qoff[i]  = (hr * Wq + wr) * Cn + c4 * 4;
        qdst[i]  = (rr * CCK + c4 * 4) * QPAD + w;
    }
    int poff[2], pdst[2];
    bool pok[2];
    #pragma unroll
    for (int i = 0; i < 2; ++i) {
        int flat = tid + i * NTHR;
        pok[i]  = (flat < TH * TW * 2);      // 512
        int f   = pok[i] ? flat : 0;
        int c4  = f & 1;
        int t   = f >> 1;
        int w   = t & (TW - 1);
        int rw  = t >> 6;
        int hr  = ho0 + rw; if (hr > Hon - 1) hr = Hon - 1;
        int wr  = wo0 + w;  if (wr > Won - 1) wr = Won - 1;
        poff[i] = (hr * Won + wr) * Cn + c4 * 4;
        pdst[i] = (rw * CCK + c4 * 4) * PPAD + w;
    }

    // ---- accumulators: [group][pair][dx], packed f32x2 ----
    unsigned long long acc[2][2][9];
    #pragma unroll
    for (int g = 0; g < 2; ++g)
        #pragma unroll
        for (int j = 0; j < 2; ++j)
            #pragma unroll
            for (int dx = 0; dx < 9; ++dx)
                acc[g][j][dx] = 0ull;

    const int r = ty + tz;                   // q tile row for this thread

    // ---- prolog: prefetch chunk 0 ----
    float4 qpf[6], ppf[2];
    #pragma unroll
    for (int i = 0; i < 6; ++i)
        qpf[i] = *(const float4*)(qb + qoff[i]);
    #pragma unroll
    for (int i = 0; i < 2; ++i)
        if (pok[i]) ppf[i] = *(const float4*)(pb + poff[i]);

    for (int k = 0; k < NCHUNK; ++k) {
        __syncthreads();    // protect smem from previous chunk's readers
        // ---- STS chunk k ----
        #pragma unroll
        for (int i = 0; i < 6; ++i) {
            q_s[qdst[i]           ] = qpf[i].x;
            q_s[qdst[i] +     QPAD] = qpf[i].y;
            q_s[qdst[i] + 2 * QPAD] = qpf[i].z;
            q_s[qdst[i] + 3 * QPAD] = qpf[i].w;
        }
        #pragma unroll
        for (int i = 0; i < 2; ++i) {
            if (pok[i]) {
                p_s[pdst[i]           ] = ppf[i].x;
                p_s[pdst[i] +     PPAD] = ppf[i].y;
                p_s[pdst[i] + 2 * PPAD] = ppf[i].z;
                p_s[pdst[i] + 3 * PPAD] = ppf[i].w;
            }
        }
        __syncthreads();

        // ---- prefetch chunk k+1 (issued before compute to maximize MLP) ----
        if (k + 1 < NCHUNK) {
            int cc = (k + 1) * CCK;
            #pragma unroll
            for (int i = 0; i < 6; ++i)
                qpf[i] = *(const float4*)(qb + qoff[i] + cc);
            #pragma unroll
            for (int i = 0; i < 2; ++i)
                if (pok[i]) ppf[i] = *(const float4*)(pb + poff[i] + cc);
        }

        // ---- compute chunk k ----
        #pragma unroll
        for (int c = 0; c < CCK; ++c) {
            const float* qrow = q_s + (r * CCK + c) * QPAD;
            const float* prow = p_s + (ty * CCK + c) * PPAD;
            #pragma unroll
            for (int g = 0; g < 2; ++g) {
                const int w0 = g * 32 + tx * 4;
                const float4 pv = *(const float4*)(prow + w0);
                unsigned long long pp[2];
                PACK2(pp[0], pv.x, pv.y);
                PACK2(pp[1], pv.z, pv.w);

                const float4 a0 = *(const float4*)(qrow + w0);
                const float4 a1 = *(const float4*)(qrow + w0 + 4);
                const float4 a2 = *(const float4*)(qrow + w0 + 8);
                float qf[12] = {a0.x, a0.y, a0.z, a0.w,
                                a1.x, a1.y, a1.z, a1.w,
                                a2.x, a2.y, a2.z, a2.w};
                unsigned long long pr[11];
                #pragma unroll
                for (int j = 0; j < 11; ++j)
                    PACK2(pr[j], qf[j], qf[j + 1]);

                #pragma unroll
                for (int dx = 0; dx < 9; ++dx) {
                    FMA2(acc[g][0][dx], pp[0], pr[dx]);       // pixels w0+0,1
                    FMA2(acc[g][1][dx], pp[1], pr[dx + 2]);   // pixels w0+2,3
                }
            }
        }
    }

    // ---- epilogue: smem-staged coalesced output, 2 slabs of 2 rows ----
    float* out_s = smem;    // [2][TW][81] = 10368 floats
    #pragma unroll
    for (int s = 0; s < 2; ++s) {
        __syncthreads();
        if ((ty >> 1) == s) {
            const int rr = ty & 1;
            #pragma unroll
            for (int g = 0; g < 2; ++g) {
                const int w0 = g * 32 + tx * 4;
                #pragma unroll
                for (int j = 0; j < 2; ++j) {
                    // pixels w0+2j, w0+2j+1
                    float* d0 = out_s + (rr * TW + w0 + 2 * j) * 81 + tz * 9;
                    float* d1 = d0 + 81;
                    #pragma unroll
                    for (int dx = 0; dx < 9; ++dx) {
                        float lo, hi;
                        UNPACK2(lo, hi, acc[g][j][dx]);
                        d0[dx] = lo;
                        d1[dx] = hi;
                    }
                }
            }
        }
        __syncthreads();
        // cooperative coalesced copy: 10368 floats, 36 per thread
        #pragma unroll
        for (int kk = 0; kk < 36; ++kk) {
            int f   = tid + kk * NTHR;
            int rr  = f / (TW * 81);
            int rem = f - rr * (TW * 81);
            int px  = rem / 81;
            int ho  = ho0 + 2 * s + rr;
            if (ho < Hon && (wo0 + px) < Won) {
                size_t dst = ((size_t)(b * Hon + ho) * Won + wo0) * 81 + rem;
                __stcs(&outg[dst], out_s[f]);
            }
        }
    }
}

extern "C" void kernel_launch(void* const* d_in, const int* in_sizes, int n_in,
                              void* d_out, int out_size)
{
    const float* p = (const float*)d_in[0];
    const float* q = (const float*)d_in[1];
    float* out = (float*)d_out;

    dim3 block(NTX, TH, NTZ);                  // 8 x 4 x 9 = 288
    dim3 grid((Won + TW - 1) / TW,             // 8
              (Hon + TH - 1) / TH,             // 126
              Bn);                             // 4
    corr9x9_sp_kernel<<<grid, block>>>(p, q, out);
}

// round 8
// speedup vs baseline: 1.5599x; 1.0008x over previous
#include <cuda_runtime.h>

// Problem constants
#define Bn   4
#define Hq   512
#define Wq   512
#define Cn   128
#define Hon  502
#define Won  502
#define OFFS 2
// Tiling: block (8,4,9); tile 4 rows x 64 cols; tz == dy
#define TH   4
#define TW   64
#define NTX  8
#define NTZ  9
#define NTHR 288
#define CCK  8
#define NCHUNK 16
#define QR   12            // TH + 8 halo rows
#define QW   72            // TW + 8 halo cols
#define QPAD 76
#define PPAD 68

// union sizes (floats)
#define TILE_FLOATS (QR*CCK*QPAD + TH*CCK*PPAD)   // 7296 + 2176 = 9472
#define OUTS_FLOATS (2*TW*81)                     // 10368
#define SMEM_FLOATS (OUTS_FLOATS > TILE_FLOATS ? OUTS_FLOATS : TILE_FLOATS)

// Packed fp32x2 helpers (sm_103a)
#define FMA2(d, a, b) asm("fma.rn.f32x2 %0, %1, %2, %0;" : "+l"(d) : "l"(a), "l"(b))
#define PACK2(r, lo, hi) asm("mov.b64 %0, {%1, %2};" : "=l"(r) : "f"(lo), "f"(hi))
#define UNPACK2(lo, hi, r) asm("mov.b64 {%0, %1}, %2;" : "=f"(lo), "=f"(hi) : "l"(r))

__global__ __launch_bounds__(NTHR, 1)
void corr9x9_sp_kernel(const float* __restrict__ pg,
                       const float* __restrict__ qg,
                       float* __restrict__ outg)
{
    __shared__ __align__(16) float smem[SMEM_FLOATS];
    float* q_s = smem;                       // [QR][CCK][QPAD]
    float* p_s = smem + QR * CCK * QPAD;     // [TH][CCK][PPAD]

    const int tx  = threadIdx.x;             // 0..7
    const int ty  = threadIdx.y;             // 0..3
    const int tz  = threadIdx.z;             // 0..8 == dy
    const int tid = tx + NTX * (ty + TH * tz);

    const int wo0 = blockIdx.x * TW;
    const int ho0 = blockIdx.y * TH;
    const int b   = blockIdx.z;

    const float* pb = pg + (size_t)b * Hon * Won * Cn;
    const float* qb = qg + (size_t)b * Hq  * Wq  * Cn;

    // ---- precompute staging offsets ----
    int qoff[6], qdst[6];
    #pragma unroll
    for (int i = 0; i < 6; ++i) {
        int flat = tid + i * NTHR;          // exactly covers QR*QW*2 = 1728
        int c4   = flat & 1;
        int t    = flat >> 1;
        int w    = t % QW;
        int rr   = t / QW;
        int hr   = ho0 + OFFS + rr; if (hr > Hq - 1) hr = Hq - 1;
        int wr   = wo0 + OFFS + w;  if (wr > Wq - 1) wr = Wq - 1;
        qoff[i]  = (hr * Wq + wr) * Cn + c4 * 4;
        qdst[i]  = (rr * CCK + c4 * 4) * QPAD + w;
    }
    int poff[2], pdst[2];
    bool pok[2];
    #pragma unroll
    for (int i = 0; i < 2; ++i) {
        int flat = tid + i * NTHR;
        pok[i]  = (flat < TH * TW * 2);      // 512
        int f   = pok[i] ? flat : 0;
        int c4  = f & 1;
        int t   = f >> 1;
        int w   = t & (TW - 1);
        int rw  = t >> 6;
        int hr  = ho0 + rw; if (hr > Hon - 1) hr = Hon - 1;
        int wr  = wo0 + w;  if (wr > Won - 1) wr = Won - 1;
        poff[i] = (hr * Won + wr) * Cn + c4 * 4;
        pdst[i] = (rw * CCK + c4 * 4) * PPAD + w;
    }

    // ---- accumulators: [group][pair][dx], packed f32x2 ----
    unsigned long long acc[2][2][9];
    #pragma unroll
    for (int g = 0; g < 2; ++g)
        #pragma unroll
        for (int j = 0; j < 2; ++j)
            #pragma unroll
            for (int dx = 0; dx < 9; ++dx)
                acc[g][j][dx] = 0ull;

    const int r = ty + tz;                   // q tile row for this thread

    // ---- prolog: prefetch chunk 0 ----
    float4 qpf[6], ppf[2];
    #pragma unroll
    for (int i = 0; i < 6; ++i)
        qpf[i] = *(const float4*)(qb + qoff[i]);
    #pragma unroll
    for (int i = 0; i < 2; ++i)
        if (pok[i]) ppf[i] = *(const float4*)(pb + poff[i]);

    for (int k = 0; k < NCHUNK; ++k) {
        __syncthreads();    // protect smem from previous chunk's readers
        // ---- STS chunk k ----
        #pragma unroll
        for (int i = 0; i < 6; ++i) {
            q_s[qdst[i]           ] = qpf[i].x;
            q_s[qdst[i] +     QPAD] = qpf[i].y;
            q_s[qdst[i] + 2 * QPAD] = qpf[i].z;
            q_s[qdst[i] + 3 * QPAD] = qpf[i].w;
        }
        #pragma unroll
        for (int i = 0; i < 2; ++i) {
            if (pok[i]) {
                p_s[pdst[i]           ] = ppf[i].x;
                p_s[pdst[i] +     PPAD] = ppf[i].y;
                p_s[pdst[i] + 2 * PPAD] = ppf[i].z;
                p_s[pdst[i] + 3 * PPAD] = ppf[i].w;
            }
        }
        __syncthreads();

        // ---- prefetch chunk k+1 (issued before compute to maximize MLP) ----
        if (k + 1 < NCHUNK) {
            int cc = (k + 1) * CCK;
            #pragma unroll
            for (int i = 0; i < 6; ++i)
                qpf[i] = *(const float4*)(qb + qoff[i] + cc);
            #pragma unroll
            for (int i = 0; i < 2; ++i)
                if (pok[i]) ppf[i] = *(const float4*)(pb + poff[i] + cc);
        }

        // ---- compute chunk k ----
        #pragma unroll
        for (int c = 0; c < CCK; ++c) {
            const float* qrow = q_s + (r * CCK + c) * QPAD;
            const float* prow = p_s + (ty * CCK + c) * PPAD;
            #pragma unroll
            for (int g = 0; g < 2; ++g) {
                const int w0 = g * 32 + tx * 4;
                const float4 pv = *(const float4*)(prow + w0);
                unsigned long long pp[2];
                PACK2(pp[0], pv.x, pv.y);
                PACK2(pp[1], pv.z, pv.w);

                const float4 a0 = *(const float4*)(qrow + w0);
                const float4 a1 = *(const float4*)(qrow + w0 + 4);
                const float4 a2 = *(const float4*)(qrow + w0 + 8);
                float qf[12] = {a0.x, a0.y, a0.z, a0.w,
                                a1.x, a1.y, a1.z, a1.w,
                                a2.x, a2.y, a2.z, a2.w};
                unsigned long long pr[11];
                #pragma unroll
                for (int j = 0; j < 11; ++j)
                    PACK2(pr[j], qf[j], qf[j + 1]);

                #pragma unroll
                for (int dx = 0; dx < 9; ++dx) {
                    FMA2(acc[g][0][dx], pp[0], pr[dx]);       // pixels w0+0,1
                    FMA2(acc[g][1][dx], pp[1], pr[dx + 2]);   // pixels w0+2,3
                }
            }
        }
    }

    // ---- epilogue: smem-staged coalesced output, 2 slabs of 2 rows ----
    float* out_s = smem;    // [2][TW][81] = 10368 floats
    #pragma unroll
    for (int s = 0; s < 2; ++s) {
        __syncthreads();
        if ((ty >> 1) == s) {
            const int rr = ty & 1;
            #pragma unroll
            for (int g = 0; g < 2; ++g) {
                const int w0 = g * 32 + tx * 4;
                #pragma unroll
                for (int j = 0; j < 2; ++j) {
                    // pixels w0+2j, w0+2j+1
                    float* d0 = out_s + (rr * TW + w0 + 2 * j) * 81 + tz * 9;
                    float* d1 = d0 + 81;
                    #pragma unroll
                    for (int dx = 0; dx < 9; ++dx) {
                        float lo, hi;
                        UNPACK2(lo, hi, acc[g][j][dx]);
                        d0[dx] = lo;
                        d1[dx] = hi;
                    }
                }
            }
        }
        __syncthreads();
        // cooperative coalesced copy: 10368 floats, 36 per thread
        #pragma unroll
        for (int kk = 0; kk < 36; ++kk) {
            int f   = tid + kk * NTHR;
            int rr  = f / (TW * 81);
            int rem = f - rr * (TW * 81);
            int px  = rem / 81;
            int ho  = ho0 + 2 * s + rr;
            if (ho < Hon && (wo0 + px) < Won) {
                size_t dst = ((size_t)(b * Hon + ho) * Won + wo0) * 81 + rem;
                __stcs(&outg[dst], out_s[f]);
            }
        }
    }
}

extern "C" void kernel_launch(void* const* d_in, const int* in_sizes, int n_in,
                              void* d_out, int out_size)
{
    const float* p = (const float*)d_in[0];
    const float* q = (const float*)d_in[1];
    float* out = (float*)d_out;

    dim3 block(NTX, TH, NTZ);                  // 8 x 4 x 9 = 288
    dim3 grid((Won + TW - 1) / TW,             // 8
              (Hon + TH - 1) / TH,             // 126
              Bn);                             // 4
    corr9x9_sp_kernel<<<grid, block>>>(p, q, out);
}